// round 11
// baseline (speedup 1.0000x reference)
#include <cuda_runtime.h>
#include <cuda_bf16.h>
#include <mma.h>
#include <math.h>

using namespace nvcuda;

// Problem constants
#define BB    2
#define SS    2048
#define DM    4096
#define HD    128
#define NH    32
#define NKV   8
#define MROWS (BB * SS)          // 4096

// Scratch (device globals: allocation-free)
__device__ float g_Q [BB * SS * NH  * HD];   // 67 MB
__device__ float g_K [BB * SS * NKV * HD];   // 16.8 MB
__device__ float g_V [BB * SS * NKV * HD];   // 16.8 MB
__device__ float g_AO[BB * SS * NH  * HD];   // 67 MB

__device__ __forceinline__ void bf16_split(float f, __nv_bfloat16& hi, __nv_bfloat16& lo)
{
    hi = __float2bfloat16(f);
    lo = __float2bfloat16(f - __bfloat162float(hi));
}

__device__ __forceinline__ __nv_bfloat162 bf2(__nv_bfloat16 a, __nv_bfloat16 b)
{
    __nv_bfloat162 r; r.x = a; r.y = b; return r;
}

// ---------------------------------------------------------------------------
// NT GEMM, split-precision bf16x3 on tensor cores (wmma):
//   C[M,N] = A[M,K] * B[N,K]^T  (fp32 in/out, fp32-class accuracy)
// 128x128 CTA tile, 256 threads = 8 warps (2 M x 4 N), warp tile 64x32,
// K-tile 32, double-buffered smem stages (one barrier per K-tile).
// ---------------------------------------------------------------------------
#define KT  32
#define LDT 40   // padded smem row (elements); 80B, multiple of 16B for wmma
#define GEMM_STAGE_ELEMS (128 * LDT)
#define GEMM_SMEM_BYTES  (2 * 4 * GEMM_STAGE_ELEMS * 2)   // 81920 B

__device__ __forceinline__ void gemm_nt_bf16x3_body(
    const float* __restrict__ A, const float* __restrict__ B,
    float* __restrict__ C, int M, int N, int K,
    int bm, int bn, __nv_bfloat16* smbf)
{
    __nv_bfloat16* Ah[2] = { smbf,                         smbf + 4 * GEMM_STAGE_ELEMS };
    __nv_bfloat16* Al[2] = { smbf + 1 * GEMM_STAGE_ELEMS,  smbf + 5 * GEMM_STAGE_ELEMS };
    __nv_bfloat16* Bh[2] = { smbf + 2 * GEMM_STAGE_ELEMS,  smbf + 6 * GEMM_STAGE_ELEMS };
    __nv_bfloat16* Bl[2] = { smbf + 3 * GEMM_STAGE_ELEMS,  smbf + 7 * GEMM_STAGE_ELEMS };

    const int tid  = threadIdx.x;
    const int warp = tid >> 5;
    const int wm   = warp >> 2;
    const int wn   = warp & 3;

    wmma::fragment<wmma::accumulator, 16, 16, 16, float> acc[4][2];
#pragma unroll
    for (int mi = 0; mi < 4; mi++)
#pragma unroll
        for (int ni = 0; ni < 2; ni++)
            wmma::fill_fragment(acc[mi][ni], 0.0f);

    const int r0 = tid >> 3;
    const int c0 = (tid & 7) * 4;

    const float* Abase = A + (size_t)(bm + r0) * K + c0;
    const float* Bbase = B + (size_t)(bn + r0) * K + c0;

    float4 pa[4], pb[4];
#pragma unroll
    for (int i = 0; i < 4; i++) {
        pa[i] = *(const float4*)(Abase + (size_t)(32 * i) * K);
        pb[i] = *(const float4*)(Bbase + (size_t)(32 * i) * K);
    }
#pragma unroll
    for (int i = 0; i < 4; i++) {
        const int row = r0 + 32 * i;
        const float va[4] = {pa[i].x, pa[i].y, pa[i].z, pa[i].w};
        const float vb[4] = {pb[i].x, pb[i].y, pb[i].z, pb[i].w};
        __nv_bfloat16 h0, l0, h1, l1;
#pragma unroll
        for (int q = 0; q < 4; q += 2) {
            bf16_split(va[q], h0, l0); bf16_split(va[q + 1], h1, l1);
            *(__nv_bfloat162*)&Ah[0][row * LDT + c0 + q] = bf2(h0, h1);
            *(__nv_bfloat162*)&Al[0][row * LDT + c0 + q] = bf2(l0, l1);
            bf16_split(vb[q], h0, l0); bf16_split(vb[q + 1], h1, l1);
            *(__nv_bfloat162*)&Bh[0][row * LDT + c0 + q] = bf2(h0, h1);
            *(__nv_bfloat162*)&Bl[0][row * LDT + c0 + q] = bf2(l0, l1);
        }
    }
    __syncthreads();

    const int nkt = K / KT;
    for (int kt = 0; kt < nkt; kt++) {
        const int buf = kt & 1;
        const bool more = (kt + 1 < nkt);

        if (more) {
            const size_t koff = (size_t)(kt + 1) * KT;
#pragma unroll
            for (int i = 0; i < 4; i++) {
                pa[i] = *(const float4*)(Abase + (size_t)(32 * i) * K + koff);
                pb[i] = *(const float4*)(Bbase + (size_t)(32 * i) * K + koff);
            }
        }

#pragma unroll
        for (int ks = 0; ks < KT; ks += 16) {
            wmma::fragment<wmma::matrix_a, 16, 16, 16, __nv_bfloat16, wmma::row_major> ah[4], al[4];
            wmma::fragment<wmma::matrix_b, 16, 16, 16, __nv_bfloat16, wmma::col_major> bh[2], bl[2];
#pragma unroll
            for (int mi = 0; mi < 4; mi++) {
                const int arow = wm * 64 + mi * 16;
                wmma::load_matrix_sync(ah[mi], &Ah[buf][arow * LDT + ks], LDT);
                wmma::load_matrix_sync(al[mi], &Al[buf][arow * LDT + ks], LDT);
            }
#pragma unroll
            for (int ni = 0; ni < 2; ni++) {
                const int brow = wn * 32 + ni * 16;
                wmma::load_matrix_sync(bh[ni], &Bh[buf][brow * LDT + ks], LDT);
                wmma::load_matrix_sync(bl[ni], &Bl[buf][brow * LDT + ks], LDT);
            }
#pragma unroll
            for (int mi = 0; mi < 4; mi++)
#pragma unroll
                for (int ni = 0; ni < 2; ni++) {
                    wmma::mma_sync(acc[mi][ni], ah[mi], bh[ni], acc[mi][ni]);
                    wmma::mma_sync(acc[mi][ni], ah[mi], bl[ni], acc[mi][ni]);
                    wmma::mma_sync(acc[mi][ni], al[mi], bh[ni], acc[mi][ni]);
                }
        }

        if (more) {
            const int nbuf = buf ^ 1;
#pragma unroll
            for (int i = 0; i < 4; i++) {
                const int row = r0 + 32 * i;
                const float va[4] = {pa[i].x, pa[i].y, pa[i].z, pa[i].w};
                const float vb[4] = {pb[i].x, pb[i].y, pb[i].z, pb[i].w};
                __nv_bfloat16 h0, l0, h1, l1;
#pragma unroll
                for (int q = 0; q < 4; q += 2) {
                    bf16_split(va[q], h0, l0); bf16_split(va[q + 1], h1, l1);
                    *(__nv_bfloat162*)&Ah[nbuf][row * LDT + c0 + q] = bf2(h0, h1);
                    *(__nv_bfloat162*)&Al[nbuf][row * LDT + c0 + q] = bf2(l0, l1);
                    bf16_split(vb[q], h0, l0); bf16_split(vb[q + 1], h1, l1);
                    *(__nv_bfloat162*)&Bh[nbuf][row * LDT + c0 + q] = bf2(h0, h1);
                    *(__nv_bfloat162*)&Bl[nbuf][row * LDT + c0 + q] = bf2(l0, l1);
                }
            }
        }
        __syncthreads();
    }

#pragma unroll
    for (int mi = 0; mi < 4; mi++)
#pragma unroll
        for (int ni = 0; ni < 2; ni++) {
            float* cp = C + (size_t)(bm + wm * 64 + mi * 16) * N + bn + wn * 32 + ni * 16;
            wmma::store_matrix_sync(cp, acc[mi][ni], N, wmma::mem_row_major);
        }
}

__global__ __launch_bounds__(256) void gemm_nt_bf16x3(
    const float* __restrict__ A, const float* __restrict__ B,
    float* __restrict__ C, int M, int N, int K)
{
    extern __shared__ __nv_bfloat16 smbf[];
    gemm_nt_bf16x3_body(A, B, C, M, N, K,
                        blockIdx.y * 128, blockIdx.x * 128, smbf);
}

// Fused Q, K, V projections in ONE launch (same A = x, three Bs).
// blockIdx.x: [0,32) -> Q (N=4096), [32,40) -> K (N=1024), [40,48) -> V (N=1024)
__global__ __launch_bounds__(256) void gemm_nt_bf16x3_qkv(
    const float* __restrict__ A,
    const float* __restrict__ Bq, float* __restrict__ Cq,
    const float* __restrict__ Bk, float* __restrict__ Ck,
    const float* __restrict__ Bv, float* __restrict__ Cv,
    int M, int K)
{
    extern __shared__ __nv_bfloat16 smbf[];
    const int bx = blockIdx.x;
    if (bx < 32) {
        gemm_nt_bf16x3_body(A, Bq, Cq, M, NH * HD, K,
                            blockIdx.y * 128, bx * 128, smbf);
    } else if (bx < 40) {
        gemm_nt_bf16x3_body(A, Bk, Ck, M, NKV * HD, K,
                            blockIdx.y * 128, (bx - 32) * 128, smbf);
    } else {
        gemm_nt_bf16x3_body(A, Bv, Cv, M, NKV * HD, K,
                            blockIdx.y * 128, (bx - 40) * 128, smbf);
    }
}

// ---------------------------------------------------------------------------
// RoPE (interleaved pairs), in-place on Q and K. Mirrors reference fp32 math.
// ---------------------------------------------------------------------------
__global__ void rope_kernel(float* __restrict__ Q, float* __restrict__ Kc,
                            const int* __restrict__ posp)
{
    long long i = (long long)blockIdx.x * blockDim.x + threadIdx.x;
    const long long total = (long long)BB * SS * (NH + NKV) * (HD / 2);
    if (i >= total) return;
    int p   = (int)(i & 63);
    long long t2 = i >> 6;
    int h   = (int)(t2 % (NH + NKV));
    long long bs = t2 / (NH + NKV);
    int s   = (int)(bs % SS);

    float t   = (float)(*posp + s);
    float e   = (float)p * (2.0f / (float)HD);
    float inv = 1.0f / powf(10000.0f, e);
    float ang = t * inv;
    float sn, cs;
    sincosf(ang, &sn, &cs);

    float* base = (h < NH)
        ? (Q  + ((bs * NH  + h)        << 7))
        : (Kc + ((bs * NKV + (h - NH)) << 7));
    float x1 = base[2 * p];
    float x2 = base[2 * p + 1];
    base[2 * p]     = x1 * cs - x2 * sn;
    base[2 * p + 1] = x1 * sn + x2 * cs;
}

// ---------------------------------------------------------------------------
// Flash-style causal GQA attention on tensor cores (wmma, bf16x3 splits).
// Block = one (batch, q-head, 64-row q tile). 256 threads = 8 warps.
// Per kv tile (64 rows), 4 barriers:
//   A: convert prefetched K,V regs -> smem hi/lo splits
//   B: S = Q K^T (bf16x3, fp32 acc; Q fragments hoisted) -> S smem
//   C: causal mask + online softmax (fp32); P hi/lo -> smem; O *= corr
//   D: O-fragment = load(Osm); O += P V (bf16x3); store(Osm)   [warp-exclusive]
// qt order reversed so heavy diagonal tiles launch first.
// ---------------------------------------------------------------------------
#define LDQK 136   // bf16 row pitch for Q/K/V tiles (mult of 8)
#define LDP  72    // bf16 row pitch for P (mult of 8)
#define LDS  68    // fp32 row pitch for S (mult of 4)
#define LDO  132   // fp32 row pitch for O (mult of 4)

#define OFF_QH  0
#define OFF_QL  (OFF_QH + 64 * LDQK * 2)          // 17408
#define OFF_KH  (OFF_QL + 64 * LDQK * 2)          // 34816
#define OFF_KL  (OFF_KH + 64 * LDQK * 2)          // 52224
#define OFF_VH  (OFF_KL + 64 * LDQK * 2)          // 69632
#define OFF_VL  (OFF_VH + 64 * LDQK * 2)          // 87040
#define OFF_S   (OFF_VL + 64 * LDQK * 2)          // 104448
#define OFF_PH  (OFF_S  + 64 * LDS * 4)           // 121856
#define OFF_PL  (OFF_PH + 64 * LDP * 2)           // 131072
#define OFF_O   (OFF_PL + 64 * LDP * 2)           // 140288
#define OFF_M   (OFF_O  + 64 * LDO * 4)           // 174080
#define OFF_L   (OFF_M  + 64 * 4)                 // 174336
#define ATTN_SMEM_BYTES (OFF_L + 64 * 4)          // 174592

__global__ __launch_bounds__(256) void attn_kernel(
    const float* __restrict__ Q, const float* __restrict__ K,
    const float* __restrict__ V, float* __restrict__ AO)
{
    extern __shared__ char smc[];
    __nv_bfloat16* Qh = (__nv_bfloat16*)(smc + OFF_QH);
    __nv_bfloat16* Ql = (__nv_bfloat16*)(smc + OFF_QL);
    __nv_bfloat16* Kh = (__nv_bfloat16*)(smc + OFF_KH);
    __nv_bfloat16* Kl = (__nv_bfloat16*)(smc + OFF_KL);
    __nv_bfloat16* Vh = (__nv_bfloat16*)(smc + OFF_VH);
    __nv_bfloat16* Vl = (__nv_bfloat16*)(smc + OFF_VL);
    float* Ssm   = (float*)(smc + OFF_S);
    __nv_bfloat16* Ph = (__nv_bfloat16*)(smc + OFF_PH);
    __nv_bfloat16* Pl = (__nv_bfloat16*)(smc + OFF_PL);
    float* Osm   = (float*)(smc + OFF_O);
    float* Msm   = (float*)(smc + OFF_M);
    float* Lsm   = (float*)(smc + OFF_L);

    const int tid  = threadIdx.x;
    const int warp = tid >> 5;
    const int qt   = (int)(gridDim.x - 1) - blockIdx.x;   // heavy tiles first
    const int h    = blockIdx.y;
    const int b    = blockIdx.z;
    const int kvh  = h >> 2;
    const float scale = 0.08838834764831845f;   // 1/sqrt(128)

    // Row/col-group mapping for elementwise phases: 4 threads per row
    const int rr = tid >> 2;          // 0..63
    const int cg = tid & 3;           // 0..3

    // --- Init: load+split Q (pre-scaled), zero O, init m/l ---
    {
        const float* qsrc = Q + (((size_t)(b * SS + qt * 64 + rr) * NH + h) << 7) + cg * 32;
#pragma unroll
        for (int k = 0; k < 32; k += 4) {
            float4 v = *(const float4*)(qsrc + k);
            const float vv[4] = {v.x, v.y, v.z, v.w};
            __nv_bfloat16 h0, l0, h1, l1;
#pragma unroll
            for (int q = 0; q < 4; q += 2) {
                bf16_split(vv[q] * scale, h0, l0);
                bf16_split(vv[q + 1] * scale, h1, l1);
                *(__nv_bfloat162*)&Qh[rr * LDQK + cg * 32 + k + q] = bf2(h0, h1);
                *(__nv_bfloat162*)&Ql[rr * LDQK + cg * 32 + k + q] = bf2(l0, l1);
            }
        }
#pragma unroll
        for (int k = 0; k < 32; k += 4)
            *(float4*)&Osm[rr * LDO + cg * 32 + k] = make_float4(0.f, 0.f, 0.f, 0.f);
        if (tid < 64) { Msm[tid] = -1e30f; Lsm[tid] = 0.0f; }
    }

    // Preload kv tile 0 into registers
    float4 kreg[8], vreg[8];
    {
        const size_t kvrow = ((size_t)(b * SS + rr) * NKV + kvh) << 7;
        const float* ksrc = K + kvrow + cg * 32;
        const float* vsrc = V + kvrow + cg * 32;
#pragma unroll
        for (int i = 0; i < 8; i++) {
            kreg[i] = *(const float4*)(ksrc + i * 4);
            vreg[i] = *(const float4*)(vsrc + i * 4);
        }
    }
    __syncthreads();

    // Hoist loop-invariant Q fragments (Phase-B layout: warp row band)
    const int wmrB = (warp >> 1) * 16;   // 0,16,32,48
    const int wncB = (warp & 1) * 32;    // 0,32
    wmma::fragment<wmma::matrix_a, 16, 16, 16, __nv_bfloat16, wmma::row_major> qah[8], qal[8];
#pragma unroll
    for (int s = 0; s < 8; s++) {
        wmma::load_matrix_sync(qah[s], &Qh[wmrB * LDQK + s * 16], LDQK);
        wmma::load_matrix_sync(qal[s], &Ql[wmrB * LDQK + s * 16], LDQK);
    }

    for (int kt = 0; kt <= qt; kt++) {
        // --- Phase A: convert prefetched K,V registers into smem splits ---
#pragma unroll
        for (int i = 0; i < 8; i++) {
            const float kk[4]  = {kreg[i].x, kreg[i].y, kreg[i].z, kreg[i].w};
            const float vvv[4] = {vreg[i].x, vreg[i].y, vreg[i].z, vreg[i].w};
            __nv_bfloat16 h0, l0, h1, l1;
#pragma unroll
            for (int q = 0; q < 4; q += 2) {
                bf16_split(kk[q], h0, l0); bf16_split(kk[q + 1], h1, l1);
                *(__nv_bfloat162*)&Kh[rr * LDQK + cg * 32 + i * 4 + q] = bf2(h0, h1);
                *(__nv_bfloat162*)&Kl[rr * LDQK + cg * 32 + i * 4 + q] = bf2(l0, l1);
                bf16_split(vvv[q], h0, l0); bf16_split(vvv[q + 1], h1, l1);
                *(__nv_bfloat162*)&Vh[rr * LDQK + cg * 32 + i * 4 + q] = bf2(h0, h1);
                *(__nv_bfloat162*)&Vl[rr * LDQK + cg * 32 + i * 4 + q] = bf2(l0, l1);
            }
        }
        __syncthreads();

        // Prefetch next kv tile (latency hidden behind Phases B-D)
        if (kt < qt) {
            const size_t kvrow = ((size_t)(b * SS + (kt + 1) * 64 + rr) * NKV + kvh) << 7;
            const float* ksrc = K + kvrow + cg * 32;
            const float* vsrc = V + kvrow + cg * 32;
#pragma unroll
            for (int i = 0; i < 8; i++) {
                kreg[i] = *(const float4*)(ksrc + i * 4);
                vreg[i] = *(const float4*)(vsrc + i * 4);
            }
        }

        // --- Phase B: S = Q K^T (64x64, k=128), warp tile 16x32 (4x2 grid) ---
        {
            wmma::fragment<wmma::accumulator, 16, 16, 16, float> sacc[2];
            wmma::fill_fragment(sacc[0], 0.0f);
            wmma::fill_fragment(sacc[1], 0.0f);
#pragma unroll
            for (int s = 0; s < 8; s++) {
                wmma::fragment<wmma::matrix_b, 16, 16, 16, __nv_bfloat16, wmma::col_major> bh[2], bl[2];
#pragma unroll
                for (int ni = 0; ni < 2; ni++) {
                    wmma::load_matrix_sync(bh[ni], &Kh[(wncB + ni * 16) * LDQK + s * 16], LDQK);
                    wmma::load_matrix_sync(bl[ni], &Kl[(wncB + ni * 16) * LDQK + s * 16], LDQK);
                }
#pragma unroll
                for (int ni = 0; ni < 2; ni++) {
                    wmma::mma_sync(sacc[ni], qah[s], bh[ni], sacc[ni]);
                    wmma::mma_sync(sacc[ni], qah[s], bl[ni], sacc[ni]);
                    wmma::mma_sync(sacc[ni], qal[s], bh[ni], sacc[ni]);
                }
            }
            wmma::store_matrix_sync(&Ssm[wmrB * LDS + wncB],      sacc[0], LDS, wmma::mem_row_major);
            wmma::store_matrix_sync(&Ssm[wmrB * LDS + wncB + 16], sacc[1], LDS, wmma::mem_row_major);
        }
        __syncthreads();

        // --- Phase C: online softmax + P splits + O *= corr ---
        {
            const bool diag = (kt == qt);
            float sv[16];
            float lmax = -1e30f;
#pragma unroll
            for (int j = 0; j < 16; j++) {
                const int col = cg * 16 + j;
                float s = Ssm[rr * LDS + col];
                if (diag && col > rr) s = -1e30f;
                sv[j] = s;
                lmax = fmaxf(lmax, s);
            }
            lmax = fmaxf(lmax, __shfl_xor_sync(0xffffffffu, lmax, 1));
            lmax = fmaxf(lmax, __shfl_xor_sync(0xffffffffu, lmax, 2));
            const float mold = Msm[rr];
            const float mnew = fmaxf(mold, lmax);
            const float corr = __expf(mold - mnew);
            float lsum = 0.f;
            float pv[16];
#pragma unroll
            for (int j = 0; j < 16; j++) {
                pv[j] = __expf(sv[j] - mnew);
                lsum += pv[j];
            }
            __nv_bfloat16 h0, l0, h1, l1;
#pragma unroll
            for (int j = 0; j < 16; j += 2) {
                bf16_split(pv[j], h0, l0); bf16_split(pv[j + 1], h1, l1);
                *(__nv_bfloat162*)&Ph[rr * LDP + cg * 16 + j] = bf2(h0, h1);
                *(__nv_bfloat162*)&Pl[rr * LDP + cg * 16 + j] = bf2(l0, l1);
            }
            lsum += __shfl_xor_sync(0xffffffffu, lsum, 1);
            lsum += __shfl_xor_sync(0xffffffffu, lsum, 2);
            if (cg == 0) {
                Msm[rr]  = mnew;
                Lsm[rr]  = Lsm[rr] * corr + lsum;
            }
            // Scale this thread's O slice by corr (same corr for the row)
#pragma unroll
            for (int k = 0; k < 32; k += 4) {
                const int idx = rr * LDO + cg * 32 + k;
                float4 o = *(float4*)&Osm[idx];
                o.x *= corr; o.y *= corr; o.z *= corr; o.w *= corr;
                *(float4*)&Osm[idx] = o;
            }
        }
        __syncthreads();

        // --- Phase D: O += P V (64x128, k=64), warp tile 32x32 (2x4 grid);
        //     accumulators seeded from Osm (warp-exclusive regions) ---
        {
            const int wmr = (warp >> 2) * 32;   // 0,32
            const int wnc = (warp & 3) * 32;    // 0,32,64,96
            wmma::fragment<wmma::accumulator, 16, 16, 16, float> pacc[2][2];
#pragma unroll
            for (int mi = 0; mi < 2; mi++)
#pragma unroll
                for (int ni = 0; ni < 2; ni++)
                    wmma::load_matrix_sync(pacc[mi][ni],
                                           &Osm[(wmr + mi * 16) * LDO + wnc + ni * 16],
                                           LDO, wmma::mem_row_major);
#pragma unroll
            for (int js = 0; js < 64; js += 16) {
                wmma::fragment<wmma::matrix_a, 16, 16, 16, __nv_bfloat16, wmma::row_major> ph[2], pl[2];
                wmma::fragment<wmma::matrix_b, 16, 16, 16, __nv_bfloat16, wmma::row_major> vh[2], vl[2];
#pragma unroll
                for (int mi = 0; mi < 2; mi++) {
                    wmma::load_matrix_sync(ph[mi], &Ph[(wmr + mi * 16) * LDP + js], LDP);
                    wmma::load_matrix_sync(pl[mi], &Pl[(wmr + mi * 16) * LDP + js], LDP);
                }
#pragma unroll
                for (int ni = 0; ni < 2; ni++) {
                    wmma::load_matrix_sync(vh[ni], &Vh[js * LDQK + wnc + ni * 16], LDQK);
                    wmma::load_matrix_sync(vl[ni], &Vl[js * LDQK + wnc + ni * 16], LDQK);
                }
#pragma unroll
                for (int mi = 0; mi < 2; mi++)
#pragma unroll
                    for (int ni = 0; ni < 2; ni++) {
                        wmma::mma_sync(pacc[mi][ni], ph[mi], vh[ni], pacc[mi][ni]);
                        wmma::mma_sync(pacc[mi][ni], ph[mi], vl[ni], pacc[mi][ni]);
                        wmma::mma_sync(pacc[mi][ni], pl[mi], vh[ni], pacc[mi][ni]);
                    }
            }
#pragma unroll
            for (int mi = 0; mi < 2; mi++)
#pragma unroll
                for (int ni = 0; ni < 2; ni++)
                    wmma::store_matrix_sync(&Osm[(wmr + mi * 16) * LDO + wnc + ni * 16],
                                            pacc[mi][ni], LDO, wmma::mem_row_major);
        }
        __syncthreads();
    }

    // --- Epilogue: normalize and store ---
    {
        const float invl = 1.0f / Lsm[rr];
        float* dst = AO + (((size_t)(b * SS + qt * 64 + rr) * NH + h) << 7) + cg * 32;
#pragma unroll
        for (int k = 0; k < 32; k += 4) {
            const int idx = rr * LDO + cg * 32 + k;
            float4 o = *(const float4*)&Osm[idx];
            *(float4*)(dst + k) = make_float4(o.x * invl, o.y * invl,
                                              o.z * invl, o.w * invl);
        }
    }
}

// ---------------------------------------------------------------------------
// Launch: x,wq,wk,wv,wo,mask,pos  ->  out (fp32, [B,S,DM])
// ---------------------------------------------------------------------------
extern "C" void kernel_launch(void* const* d_in, const int* in_sizes, int n_in,
                              void* d_out, int out_size)
{
    const float* x  = (const float*)d_in[0];
    const float* wq = (const float*)d_in[1];
    const float* wk = (const float*)d_in[2];
    const float* wv = (const float*)d_in[3];
    const float* wo = (const float*)d_in[4];
    const int*  pos = (const int*)  d_in[6];
    float* out = (float*)d_out;

    float *q, *k, *v, *ao;
    cudaGetSymbolAddress((void**)&q,  g_Q);
    cudaGetSymbolAddress((void**)&k,  g_K);
    cudaGetSymbolAddress((void**)&v,  g_V);
    cudaGetSymbolAddress((void**)&ao, g_AO);

    cudaFuncSetAttribute(gemm_nt_bf16x3,
                         cudaFuncAttributeMaxDynamicSharedMemorySize,
                         GEMM_SMEM_BYTES);
    cudaFuncSetAttribute(gemm_nt_bf16x3_qkv,
                         cudaFuncAttributeMaxDynamicSharedMemorySize,
                         GEMM_SMEM_BYTES);
    cudaFuncSetAttribute(attn_kernel,
                         cudaFuncAttributeMaxDynamicSharedMemorySize,
                         ATTN_SMEM_BYTES);

    // Fused Q+K+V projection: 48 x 32 grid (Q: 32 cols, K: 8, V: 8)
    dim3 gqkv(48, MROWS / 128);
    gemm_nt_bf16x3_qkv<<<gqkv, 256, GEMM_SMEM_BYTES>>>(
        x, wq, q, wk, k, wv, v, MROWS, DM);

    {
        long long total = (long long)BB * SS * (NH + NKV) * (HD / 2);
        int blocks = (int)((total + 255) / 256);
        rope_kernel<<<blocks, 256>>>(q, k, pos);
    }

    dim3 ga(SS / 64, NH, BB);                // 32 x 32 x 2
    attn_kernel<<<ga, 256, ATTN_SMEM_BYTES>>>(q, k, v, ao);

    dim3 gq(DM / 128, MROWS / 128);          // 32 x 32
    gemm_nt_bf16x3<<<gq, 256, GEMM_SMEM_BYTES>>>(ao, wo, out, MROWS, DM, DM);
}

// round 14
// speedup vs baseline: 1.0549x; 1.0549x over previous
#include <cuda_runtime.h>
#include <cuda_bf16.h>
#include <mma.h>
#include <math.h>

using namespace nvcuda;

// Problem constants
#define BB    2
#define SS    2048
#define DM    4096
#define HD    128
#define NH    32
#define NKV   8
#define MROWS (BB * SS)          // 4096

// Scratch (device globals: allocation-free)
__device__ float g_Q [BB * SS * NH  * HD];   // fp32 QKV-GEMM outputs
__device__ float g_K [BB * SS * NKV * HD];
__device__ float g_V [BB * SS * NKV * HD];
__device__ float g_AO[BB * SS * NH  * HD];
// Pre-split bf16 hi/lo operands for attention (written by rope_split)
__device__ __nv_bfloat16 g_Qh[BB * SS * NH  * HD];
__device__ __nv_bfloat16 g_Ql[BB * SS * NH  * HD];
__device__ __nv_bfloat16 g_Kh[BB * SS * NKV * HD];
__device__ __nv_bfloat16 g_Kl[BB * SS * NKV * HD];
__device__ __nv_bfloat16 g_Vh[BB * SS * NKV * HD];
__device__ __nv_bfloat16 g_Vl[BB * SS * NKV * HD];

__device__ __forceinline__ void bf16_split(float f, __nv_bfloat16& hi, __nv_bfloat16& lo)
{
    hi = __float2bfloat16(f);
    lo = __float2bfloat16(f - __bfloat162float(hi));
}

__device__ __forceinline__ __nv_bfloat162 bf2(__nv_bfloat16 a, __nv_bfloat16 b)
{
    __nv_bfloat162 r; r.x = a; r.y = b; return r;
}

// ---------------------------------------------------------------------------
// NT GEMM, split-precision bf16x3 on tensor cores (wmma). Unchanged (banked).
// ---------------------------------------------------------------------------
#define KT  32
#define LDT 40
#define GEMM_STAGE_ELEMS (128 * LDT)
#define GEMM_SMEM_BYTES  (2 * 4 * GEMM_STAGE_ELEMS * 2)   // 81920 B

__device__ __forceinline__ void gemm_nt_bf16x3_body(
    const float* __restrict__ A, const float* __restrict__ B,
    float* __restrict__ C, int M, int N, int K,
    int bm, int bn, __nv_bfloat16* smbf)
{
    __nv_bfloat16* Ah[2] = { smbf,                         smbf + 4 * GEMM_STAGE_ELEMS };
    __nv_bfloat16* Al[2] = { smbf + 1 * GEMM_STAGE_ELEMS,  smbf + 5 * GEMM_STAGE_ELEMS };
    __nv_bfloat16* Bh[2] = { smbf + 2 * GEMM_STAGE_ELEMS,  smbf + 6 * GEMM_STAGE_ELEMS };
    __nv_bfloat16* Bl[2] = { smbf + 3 * GEMM_STAGE_ELEMS,  smbf + 7 * GEMM_STAGE_ELEMS };

    const int tid  = threadIdx.x;
    const int warp = tid >> 5;
    const int wm   = warp >> 2;
    const int wn   = warp & 3;

    wmma::fragment<wmma::accumulator, 16, 16, 16, float> acc[4][2];
#pragma unroll
    for (int mi = 0; mi < 4; mi++)
#pragma unroll
        for (int ni = 0; ni < 2; ni++)
            wmma::fill_fragment(acc[mi][ni], 0.0f);

    const int r0 = tid >> 3;
    const int c0 = (tid & 7) * 4;

    const float* Abase = A + (size_t)(bm + r0) * K + c0;
    const float* Bbase = B + (size_t)(bn + r0) * K + c0;

    float4 pa[4], pb[4];
#pragma unroll
    for (int i = 0; i < 4; i++) {
        pa[i] = *(const float4*)(Abase + (size_t)(32 * i) * K);
        pb[i] = *(const float4*)(Bbase + (size_t)(32 * i) * K);
    }
#pragma unroll
    for (int i = 0; i < 4; i++) {
        const int row = r0 + 32 * i;
        const float va[4] = {pa[i].x, pa[i].y, pa[i].z, pa[i].w};
        const float vb[4] = {pb[i].x, pb[i].y, pb[i].z, pb[i].w};
        __nv_bfloat16 h0, l0, h1, l1;
#pragma unroll
        for (int q = 0; q < 4; q += 2) {
            bf16_split(va[q], h0, l0); bf16_split(va[q + 1], h1, l1);
            *(__nv_bfloat162*)&Ah[0][row * LDT + c0 + q] = bf2(h0, h1);
            *(__nv_bfloat162*)&Al[0][row * LDT + c0 + q] = bf2(l0, l1);
            bf16_split(vb[q], h0, l0); bf16_split(vb[q + 1], h1, l1);
            *(__nv_bfloat162*)&Bh[0][row * LDT + c0 + q] = bf2(h0, h1);
            *(__nv_bfloat162*)&Bl[0][row * LDT + c0 + q] = bf2(l0, l1);
        }
    }
    __syncthreads();

    const int nkt = K / KT;
    for (int kt = 0; kt < nkt; kt++) {
        const int buf = kt & 1;
        const bool more = (kt + 1 < nkt);

        if (more) {
            const size_t koff = (size_t)(kt + 1) * KT;
#pragma unroll
            for (int i = 0; i < 4; i++) {
                pa[i] = *(const float4*)(Abase + (size_t)(32 * i) * K + koff);
                pb[i] = *(const float4*)(Bbase + (size_t)(32 * i) * K + koff);
            }
        }

#pragma unroll
        for (int ks = 0; ks < KT; ks += 16) {
            wmma::fragment<wmma::matrix_a, 16, 16, 16, __nv_bfloat16, wmma::row_major> ah[4], al[4];
            wmma::fragment<wmma::matrix_b, 16, 16, 16, __nv_bfloat16, wmma::col_major> bh[2], bl[2];
#pragma unroll
            for (int mi = 0; mi < 4; mi++) {
                const int arow = wm * 64 + mi * 16;
                wmma::load_matrix_sync(ah[mi], &Ah[buf][arow * LDT + ks], LDT);
                wmma::load_matrix_sync(al[mi], &Al[buf][arow * LDT + ks], LDT);
            }
#pragma unroll
            for (int ni = 0; ni < 2; ni++) {
                const int brow = wn * 32 + ni * 16;
                wmma::load_matrix_sync(bh[ni], &Bh[buf][brow * LDT + ks], LDT);
                wmma::load_matrix_sync(bl[ni], &Bl[buf][brow * LDT + ks], LDT);
            }
#pragma unroll
            for (int mi = 0; mi < 4; mi++)
#pragma unroll
                for (int ni = 0; ni < 2; ni++) {
                    wmma::mma_sync(acc[mi][ni], ah[mi], bh[ni], acc[mi][ni]);
                    wmma::mma_sync(acc[mi][ni], ah[mi], bl[ni], acc[mi][ni]);
                    wmma::mma_sync(acc[mi][ni], al[mi], bh[ni], acc[mi][ni]);
                }
        }

        if (more) {
            const int nbuf = buf ^ 1;
#pragma unroll
            for (int i = 0; i < 4; i++) {
                const int row = r0 + 32 * i;
                const float va[4] = {pa[i].x, pa[i].y, pa[i].z, pa[i].w};
                const float vb[4] = {pb[i].x, pb[i].y, pb[i].z, pb[i].w};
                __nv_bfloat16 h0, l0, h1, l1;
#pragma unroll
                for (int q = 0; q < 4; q += 2) {
                    bf16_split(va[q], h0, l0); bf16_split(va[q + 1], h1, l1);
                    *(__nv_bfloat162*)&Ah[nbuf][row * LDT + c0 + q] = bf2(h0, h1);
                    *(__nv_bfloat162*)&Al[nbuf][row * LDT + c0 + q] = bf2(l0, l1);
                    bf16_split(vb[q], h0, l0); bf16_split(vb[q + 1], h1, l1);
                    *(__nv_bfloat162*)&Bh[nbuf][row * LDT + c0 + q] = bf2(h0, h1);
                    *(__nv_bfloat162*)&Bl[nbuf][row * LDT + c0 + q] = bf2(l0, l1);
                }
            }
        }
        __syncthreads();
    }

#pragma unroll
    for (int mi = 0; mi < 4; mi++)
#pragma unroll
        for (int ni = 0; ni < 2; ni++) {
            float* cp = C + (size_t)(bm + wm * 64 + mi * 16) * N + bn + wn * 32 + ni * 16;
            wmma::store_matrix_sync(cp, acc[mi][ni], N, wmma::mem_row_major);
        }
}

__global__ __launch_bounds__(256) void gemm_nt_bf16x3(
    const float* __restrict__ A, const float* __restrict__ B,
    float* __restrict__ C, int M, int N, int K)
{
    extern __shared__ __nv_bfloat16 smbf[];
    gemm_nt_bf16x3_body(A, B, C, M, N, K,
                        blockIdx.y * 128, blockIdx.x * 128, smbf);
}

// Fused Q, K, V projections in ONE launch.
__global__ __launch_bounds__(256) void gemm_nt_bf16x3_qkv(
    const float* __restrict__ A,
    const float* __restrict__ Bq, float* __restrict__ Cq,
    const float* __restrict__ Bk, float* __restrict__ Ck,
    const float* __restrict__ Bv, float* __restrict__ Cv,
    int M, int K)
{
    extern __shared__ __nv_bfloat16 smbf[];
    const int bx = blockIdx.x;
    if (bx < 32) {
        gemm_nt_bf16x3_body(A, Bq, Cq, M, NH * HD, K,
                            blockIdx.y * 128, bx * 128, smbf);
    } else if (bx < 40) {
        gemm_nt_bf16x3_body(A, Bk, Ck, M, NKV * HD, K,
                            blockIdx.y * 128, (bx - 32) * 128, smbf);
    } else {
        gemm_nt_bf16x3_body(A, Bv, Cv, M, NKV * HD, K,
                            blockIdx.y * 128, (bx - 40) * 128, smbf);
    }
}

// ---------------------------------------------------------------------------
// RoPE + bf16 hi/lo pre-split. One thread per 4 pairs (8 elements).
// ---------------------------------------------------------------------------
#define QPAIRS ((long long)BB * SS * NH  * (HD / 2))   // 8388608
#define KPAIRS ((long long)BB * SS * NKV * (HD / 2))   // 2097152
#define QGRP   (QPAIRS / 4)
#define KGRP   (KPAIRS / 4)

__global__ void rope_split_kernel(
    const float* __restrict__ Q, const float* __restrict__ K,
    const float* __restrict__ V,
    __nv_bfloat16* __restrict__ Qh, __nv_bfloat16* __restrict__ Ql,
    __nv_bfloat16* __restrict__ Kh, __nv_bfloat16* __restrict__ Kl,
    __nv_bfloat16* __restrict__ Vh, __nv_bfloat16* __restrict__ Vl,
    const int* __restrict__ posp)
{
    const long long g = (long long)blockIdx.x * blockDim.x + threadIdx.x;
    const long long total = QGRP + 2 * KGRP;
    if (g >= total) return;
    const float scale = 0.08838834764831845f;   // 1/sqrt(128)

    if (g < QGRP + KGRP) {
        const bool isQ = (g < QGRP);
        const long long j0 = (isQ ? g : (g - QGRP)) * 4;   // pair index
        const int p0 = (int)(j0 & 63);
        const long long t2 = j0 >> 6;                      // (b*SS+s)*nheads + h
        const int nheads = isQ ? NH : NKV;
        const long long bs = t2 / nheads;
        const int s = (int)(bs % SS);
        const float t = (float)(*posp + s);

        const size_t base = (size_t)t2 * HD + 2 * p0;      // 8 consecutive floats
        const float* src = isQ ? Q : K;
        float4 va = *(const float4*)(src + base);
        float4 vb = *(const float4*)(src + base + 4);
        float xin[8] = {va.x, va.y, va.z, va.w, vb.x, vb.y, vb.z, vb.w};

        __nv_bfloat16 hh[8], ll[8];
#pragma unroll
        for (int qi = 0; qi < 4; qi++) {
            const int p = p0 + qi;
            float e   = (float)p * (2.0f / (float)HD);
            float inv = 1.0f / powf(10000.0f, e);
            float ang = t * inv;
            float sn, cs;
            sincosf(ang, &sn, &cs);
            float x1 = xin[2 * qi], x2 = xin[2 * qi + 1];
            float o1 = x1 * cs - x2 * sn;
            float o2 = x1 * sn + x2 * cs;
            if (isQ) { o1 *= scale; o2 *= scale; }
            bf16_split(o1, hh[2 * qi],     ll[2 * qi]);
            bf16_split(o2, hh[2 * qi + 1], ll[2 * qi + 1]);
        }
        __nv_bfloat16* dh = isQ ? Qh : Kh;
        __nv_bfloat16* dl = isQ ? Ql : Kl;
        *(uint4*)(dh + base) = *(const uint4*)hh;
        *(uint4*)(dl + base) = *(const uint4*)ll;
    } else {
        const long long j = g - QGRP - KGRP;
        const size_t base = (size_t)j * 8;
        float4 va = *(const float4*)(V + base);
        float4 vb = *(const float4*)(V + base + 4);
        float xin[8] = {va.x, va.y, va.z, va.w, vb.x, vb.y, vb.z, vb.w};
        __nv_bfloat16 hh[8], ll[8];
#pragma unroll
        for (int qi = 0; qi < 8; qi++)
            bf16_split(xin[qi], hh[qi], ll[qi]);
        *(uint4*)(Vh + base) = *(const uint4*)hh;
        *(uint4*)(Vl + base) = *(const uint4*)ll;
    }
}

// ---------------------------------------------------------------------------
// Flash-style causal GQA attention on tensor cores (wmma, bf16x3 splits).
// Operands pre-split in gmem: Phase A is a pure uint4 copy (no conversion).
// Block = one (batch, q-head, 64-row q tile). 256 threads = 8 warps.
// ---------------------------------------------------------------------------
#define LDQK 136
#define LDP  72
#define LDS  68
#define LDO  132

#define OFF_QH  0
#define OFF_QL  (OFF_QH + 64 * LDQK * 2)
#define OFF_KH  (OFF_QL + 64 * LDQK * 2)
#define OFF_KL  (OFF_KH + 64 * LDQK * 2)
#define OFF_VH  (OFF_KL + 64 * LDQK * 2)
#define OFF_VL  (OFF_VH + 64 * LDQK * 2)
#define OFF_S   (OFF_VL + 64 * LDQK * 2)
#define OFF_PH  (OFF_S  + 64 * LDS * 4)
#define OFF_PL  (OFF_PH + 64 * LDP * 2)
#define OFF_O   (OFF_PL + 64 * LDP * 2)
#define OFF_M   (OFF_O  + 64 * LDO * 4)
#define OFF_L   (OFF_M  + 64 * 4)
#define ATTN_SMEM_BYTES (OFF_L + 64 * 4)          // 174592

__global__ __launch_bounds__(256) void attn_kernel(
    const __nv_bfloat16* __restrict__ Qh, const __nv_bfloat16* __restrict__ Ql,
    const __nv_bfloat16* __restrict__ Kh, const __nv_bfloat16* __restrict__ Kl,
    const __nv_bfloat16* __restrict__ Vh, const __nv_bfloat16* __restrict__ Vl,
    float* __restrict__ AO)
{
    extern __shared__ char smc[];
    __nv_bfloat16* QhS = (__nv_bfloat16*)(smc + OFF_QH);
    __nv_bfloat16* QlS = (__nv_bfloat16*)(smc + OFF_QL);
    __nv_bfloat16* KhS = (__nv_bfloat16*)(smc + OFF_KH);
    __nv_bfloat16* KlS = (__nv_bfloat16*)(smc + OFF_KL);
    __nv_bfloat16* VhS = (__nv_bfloat16*)(smc + OFF_VH);
    __nv_bfloat16* VlS = (__nv_bfloat16*)(smc + OFF_VL);
    float* Ssm   = (float*)(smc + OFF_S);
    __nv_bfloat16* Ph = (__nv_bfloat16*)(smc + OFF_PH);
    __nv_bfloat16* Pl = (__nv_bfloat16*)(smc + OFF_PL);
    float* Osm   = (float*)(smc + OFF_O);
    float* Msm   = (float*)(smc + OFF_M);
    float* Lsm   = (float*)(smc + OFF_L);

    const int tid  = threadIdx.x;
    const int warp = tid >> 5;
    const int qt   = (int)(gridDim.x - 1) - blockIdx.x;   // heavy tiles first
    const int h    = blockIdx.y;
    const int b    = blockIdx.z;
    const int kvh  = h >> 2;

    const int rr = tid >> 2;          // 0..63
    const int cg = tid & 3;           // 0..3
    const int sbase = rr * LDQK + cg * 32;   // common smem base for QKV copies

    // --- Init: copy pre-split Q tile, zero O, init m/l ---
    {
        const size_t qoff = (((size_t)(b * SS + qt * 64 + rr) * NH + h) << 7) + cg * 32;
#pragma unroll
        for (int j = 0; j < 4; j++) {
            *(uint4*)&QhS[sbase + j * 8] = *(const uint4*)(Qh + qoff + j * 8);
            *(uint4*)&QlS[sbase + j * 8] = *(const uint4*)(Ql + qoff + j * 8);
        }
#pragma unroll
        for (int k = 0; k < 32; k += 4)
            *(float4*)&Osm[rr * LDO + cg * 32 + k] = make_float4(0.f, 0.f, 0.f, 0.f);
        if (tid < 64) { Msm[tid] = -1e30f; Lsm[tid] = 0.0f; }
    }

    // Preload kv tile 0 into registers (pre-split bf16, as uint4)
    uint4 kh4[4], kl4[4], vh4[4], vl4[4];
    {
        const size_t kvoff = (((size_t)(b * SS + rr) * NKV + kvh) << 7) + cg * 32;
#pragma unroll
        for (int j = 0; j < 4; j++) {
            kh4[j] = *(const uint4*)(Kh + kvoff + j * 8);
            kl4[j] = *(const uint4*)(Kl + kvoff + j * 8);
            vh4[j] = *(const uint4*)(Vh + kvoff + j * 8);
            vl4[j] = *(const uint4*)(Vl + kvoff + j * 8);
        }
    }
    __syncthreads();

    // Hoist loop-invariant Q fragments (Phase-B layout: warp row band)
    const int wmrB = (warp >> 1) * 16;   // 0,16,32,48
    const int wncB = (warp & 1) * 32;    // 0,32
    wmma::fragment<wmma::matrix_a, 16, 16, 16, __nv_bfloat16, wmma::row_major> qah[8], qal[8];
#pragma unroll
    for (int s = 0; s < 8; s++) {
        wmma::load_matrix_sync(qah[s], &QhS[wmrB * LDQK + s * 16], LDQK);
        wmma::load_matrix_sync(qal[s], &QlS[wmrB * LDQK + s * 16], LDQK);
    }

    for (int kt = 0; kt <= qt; kt++) {
        // --- Phase A: pure uint4 copy of prefetched K/V into smem ---
#pragma unroll
        for (int j = 0; j < 4; j++) {
            *(uint4*)&KhS[sbase + j * 8] = kh4[j];
            *(uint4*)&KlS[sbase + j * 8] = kl4[j];
            *(uint4*)&VhS[sbase + j * 8] = vh4[j];
            *(uint4*)&VlS[sbase + j * 8] = vl4[j];
        }
        __syncthreads();

        // Prefetch next kv tile (latency hidden behind Phases B-D)
        if (kt < qt) {
            const size_t kvoff =
                (((size_t)(b * SS + (kt + 1) * 64 + rr) * NKV + kvh) << 7) + cg * 32;
#pragma unroll
            for (int j = 0; j < 4; j++) {
                kh4[j] = *(const uint4*)(Kh + kvoff + j * 8);
                kl4[j] = *(const uint4*)(Kl + kvoff + j * 8);
                vh4[j] = *(const uint4*)(Vh + kvoff + j * 8);
                vl4[j] = *(const uint4*)(Vl + kvoff + j * 8);
            }
        }

        // --- Phase B: S = Q K^T (64x64, k=128), warp tile 16x32 (4x2 grid) ---
        {
            wmma::fragment<wmma::accumulator, 16, 16, 16, float> sacc[2];
            wmma::fill_fragment(sacc[0], 0.0f);
            wmma::fill_fragment(sacc[1], 0.0f);
#pragma unroll
            for (int s = 0; s < 8; s++) {
                wmma::fragment<wmma::matrix_b, 16, 16, 16, __nv_bfloat16, wmma::col_major> bh[2], bl[2];
#pragma unroll
                for (int ni = 0; ni < 2; ni++) {
                    wmma::load_matrix_sync(bh[ni], &KhS[(wncB + ni * 16) * LDQK + s * 16], LDQK);
                    wmma::load_matrix_sync(bl[ni], &KlS[(wncB + ni * 16) * LDQK + s * 16], LDQK);
                }
#pragma unroll
                for (int ni = 0; ni < 2; ni++) {
                    wmma::mma_sync(sacc[ni], qah[s], bh[ni], sacc[ni]);
                    wmma::mma_sync(sacc[ni], qah[s], bl[ni], sacc[ni]);
                    wmma::mma_sync(sacc[ni], qal[s], bh[ni], sacc[ni]);
                }
            }
            wmma::store_matrix_sync(&Ssm[wmrB * LDS + wncB],      sacc[0], LDS, wmma::mem_row_major);
            wmma::store_matrix_sync(&Ssm[wmrB * LDS + wncB + 16], sacc[1], LDS, wmma::mem_row_major);
        }
        __syncthreads();

        // --- Phase C: online softmax + P splits + O *= corr ---
        {
            const bool diag = (kt == qt);
            float sv[16];
            float lmax = -1e30f;
#pragma unroll
            for (int j = 0; j < 16; j++) {
                const int col = cg * 16 + j;
                float s = Ssm[rr * LDS + col];
                if (diag && col > rr) s = -1e30f;
                sv[j] = s;
                lmax = fmaxf(lmax, s);
            }
            lmax = fmaxf(lmax, __shfl_xor_sync(0xffffffffu, lmax, 1));
            lmax = fmaxf(lmax, __shfl_xor_sync(0xffffffffu, lmax, 2));
            const float mold = Msm[rr];
            const float mnew = fmaxf(mold, lmax);
            const float corr = __expf(mold - mnew);
            float lsum = 0.f;
            float pv[16];
#pragma unroll
            for (int j = 0; j < 16; j++) {
                pv[j] = __expf(sv[j] - mnew);
                lsum += pv[j];
            }
            __nv_bfloat16 h0, l0, h1, l1;
#pragma unroll
            for (int j = 0; j < 16; j += 2) {
                bf16_split(pv[j], h0, l0); bf16_split(pv[j + 1], h1, l1);
                *(__nv_bfloat162*)&Ph[rr * LDP + cg * 16 + j] = bf2(h0, h1);
                *(__nv_bfloat162*)&Pl[rr * LDP + cg * 16 + j] = bf2(l0, l1);
            }
            lsum += __shfl_xor_sync(0xffffffffu, lsum, 1);
            lsum += __shfl_xor_sync(0xffffffffu, lsum, 2);
            if (cg == 0) {
                Msm[rr]  = mnew;
                Lsm[rr]  = Lsm[rr] * corr + lsum;
            }
#pragma unroll
            for (int k = 0; k < 32; k += 4) {
                const int idx = rr * LDO + cg * 32 + k;
                float4 o = *(float4*)&Osm[idx];
                o.x *= corr; o.y *= corr; o.z *= corr; o.w *= corr;
                *(float4*)&Osm[idx] = o;
            }
        }
        __syncthreads();

        // --- Phase D: O += P V, warp tile 32x32 (2x4 grid), seeded from Osm ---
        {
            const int wmr = (warp >> 2) * 32;
            const int wnc = (warp & 3) * 32;
            wmma::fragment<wmma::accumulator, 16, 16, 16, float> pacc[2][2];
#pragma unroll
            for (int mi = 0; mi < 2; mi++)
#pragma unroll
                for (int ni = 0; ni < 2; ni++)
                    wmma::load_matrix_sync(pacc[mi][ni],
                                           &Osm[(wmr + mi * 16) * LDO + wnc + ni * 16],
                                           LDO, wmma::mem_row_major);
#pragma unroll
            for (int js = 0; js < 64; js += 16) {
                wmma::fragment<wmma::matrix_a, 16, 16, 16, __nv_bfloat16, wmma::row_major> ph[2], pl[2];
                wmma::fragment<wmma::matrix_b, 16, 16, 16, __nv_bfloat16, wmma::row_major> vh[2], vl[2];
#pragma unroll
                for (int mi = 0; mi < 2; mi++) {
                    wmma::load_matrix_sync(ph[mi], &Ph[(wmr + mi * 16) * LDP + js], LDP);
                    wmma::load_matrix_sync(pl[mi], &Pl[(wmr + mi * 16) * LDP + js], LDP);
                }
#pragma unroll
                for (int ni = 0; ni < 2; ni++) {
                    wmma::load_matrix_sync(vh[ni], &VhS[js * LDQK + wnc + ni * 16], LDQK);
                    wmma::load_matrix_sync(vl[ni], &VlS[js * LDQK + wnc + ni * 16], LDQK);
                }
#pragma unroll
                for (int mi = 0; mi < 2; mi++)
#pragma unroll
                    for (int ni = 0; ni < 2; ni++) {
                        wmma::mma_sync(pacc[mi][ni], ph[mi], vh[ni], pacc[mi][ni]);
                        wmma::mma_sync(pacc[mi][ni], ph[mi], vl[ni], pacc[mi][ni]);
                        wmma::mma_sync(pacc[mi][ni], pl[mi], vh[ni], pacc[mi][ni]);
                    }
            }
#pragma unroll
            for (int mi = 0; mi < 2; mi++)
#pragma unroll
                for (int ni = 0; ni < 2; ni++)
                    wmma::store_matrix_sync(&Osm[(wmr + mi * 16) * LDO + wnc + ni * 16],
                                            pacc[mi][ni], LDO, wmma::mem_row_major);
        }
        __syncthreads();
    }

    // --- Epilogue: normalize and store ---
    {
        const float invl = 1.0f / Lsm[rr];
        float* dst = AO + (((size_t)(b * SS + qt * 64 + rr) * NH + h) << 7) + cg * 32;
#pragma unroll
        for (int k = 0; k < 32; k += 4) {
            const int idx = rr * LDO + cg * 32 + k;
            float4 o = *(const float4*)&Osm[idx];
            *(float4*)(dst + k) = make_float4(o.x * invl, o.y * invl,
                                              o.z * invl, o.w * invl);
        }
    }
}

// ---------------------------------------------------------------------------
// Launch: x,wq,wk,wv,wo,mask,pos  ->  out (fp32, [B,S,DM])
// ---------------------------------------------------------------------------
extern "C" void kernel_launch(void* const* d_in, const int* in_sizes, int n_in,
                              void* d_out, int out_size)
{
    const float* x  = (const float*)d_in[0];
    const float* wq = (const float*)d_in[1];
    const float* wk = (const float*)d_in[2];
    const float* wv = (const float*)d_in[3];
    const float* wo = (const float*)d_in[4];
    const int*  pos = (const int*)  d_in[6];
    float* out = (float*)d_out;

    float *q, *k, *v, *ao;
    __nv_bfloat16 *qh, *ql, *kh, *kl, *vh, *vl;
    cudaGetSymbolAddress((void**)&q,  g_Q);
    cudaGetSymbolAddress((void**)&k,  g_K);
    cudaGetSymbolAddress((void**)&v,  g_V);
    cudaGetSymbolAddress((void**)&ao, g_AO);
    cudaGetSymbolAddress((void**)&qh, g_Qh);
    cudaGetSymbolAddress((void**)&ql, g_Ql);
    cudaGetSymbolAddress((void**)&kh, g_Kh);
    cudaGetSymbolAddress((void**)&kl, g_Kl);
    cudaGetSymbolAddress((void**)&vh, g_Vh);
    cudaGetSymbolAddress((void**)&vl, g_Vl);

    cudaFuncSetAttribute(gemm_nt_bf16x3,
                         cudaFuncAttributeMaxDynamicSharedMemorySize,
                         GEMM_SMEM_BYTES);
    cudaFuncSetAttribute(gemm_nt_bf16x3_qkv,
                         cudaFuncAttributeMaxDynamicSharedMemorySize,
                         GEMM_SMEM_BYTES);
    cudaFuncSetAttribute(attn_kernel,
                         cudaFuncAttributeMaxDynamicSharedMemorySize,
                         ATTN_SMEM_BYTES);

    // Fused Q+K+V projection: 48 x 32 grid
    dim3 gqkv(48, MROWS / 128);
    gemm_nt_bf16x3_qkv<<<gqkv, 256, GEMM_SMEM_BYTES>>>(
        x, wq, q, wk, k, wv, v, MROWS, DM);

    // RoPE + pre-split (4 pairs per thread)
    {
        long long total = QGRP + 2 * KGRP;
        int blocks = (int)((total + 255) / 256);
        rope_split_kernel<<<blocks, 256>>>(q, k, v, qh, ql, kh, kl, vh, vl, pos);
    }

    dim3 ga(SS / 64, NH, BB);                // 32 x 32 x 2
    attn_kernel<<<ga, 256, ATTN_SMEM_BYTES>>>(qh, ql, kh, kl, vh, vl, ao);

    dim3 gq(DM / 128, MROWS / 128);          // 32 x 32
    gemm_nt_bf16x3<<<gq, 256, GEMM_SMEM_BYTES>>>(ao, wo, out, MROWS, DM, DM);
}